// round 13
// baseline (speedup 1.0000x reference)
#include <cuda_runtime.h>
#include <math.h>

#define Nn     16384
#define D_INc  256
#define HIDD   256
#define D_OUTc 256
#define Ff     8
#define Ll     4
#define IN_CH  272          // 2*8 + 256
#define GAMMAf 0.5f

// ---------------- device scratch (no allocations allowed) ----------------
__device__ __align__(16) float g_cs[2][Ll][Ff];
__device__ __align__(16) float g_Hm[Nn][16];      // cols 0-7: tri, 8-15: cl4

__device__ __forceinline__ float softplusf(float x) {
    return (x > 20.f) ? x : log1pf(expf(x));
}

__device__ __forceinline__ void red4(float* p, float a, float b, float c, float d) {
    asm volatile("red.global.add.v4.f32 [%0], {%1, %2, %3, %4};"
                 :: "l"(p), "f"(a), "f"(b), "f"(c), "f"(d) : "memory");
}

// packed dual-fp32 FMA (Blackwell f32x2) -------------------------------
#define FFMA2(acc, a, b) \
    asm("fma.rn.f32x2 %0, %1, %2, %0;" : "+l"(acc) : "l"(a), "l"(b))
#define DUP2(p, x) \
    asm("mov.b64 %0, {%1, %1};" : "=l"(p) : "r"(x))
#define UNPK2(lo, hi, p) \
    asm("mov.b64 {%0, %1}, %2;" : "=r"(lo), "=r"(hi) : "l"(p))

// register-free async gmem->smem 16B copy (LDGSTS)
#define CPA16(dst, src) do {                                              \
    unsigned _s = (unsigned)__cvta_generic_to_shared(dst);                \
    asm volatile("cp.async.cg.shared.global [%0], [%1], 16;"              \
                 :: "r"(_s), "l"(src));                                   \
} while (0)
#define CP_COMMIT() asm volatile("cp.async.commit_group;" ::: "memory")
#define CP_WAIT0()  asm volatile("cp.async.wait_group 0;" ::: "memory")

// ---------------- kernel 1: filter traces + coefficients ----------------
__global__ void setup_kernel(const float* __restrict__ Wt,
                             const float* __restrict__ Wc,
                             const float* __restrict__ lg) {
    int t = threadIdx.x;
    if (t >= 16) return;
    int which = t >> 3;
    int f = t & 7;
    int S = which ? 4 : 3;
    const float* W = which ? (Wc + f * 16) : (Wt + f * 9);

    float Wm[4][4], Sf[4][4];
    for (int i = 0; i < S; i++)
        for (int j = 0; j < S; j++)
            Wm[i][j] = softplusf(W[i * S + j]);
    for (int i = 0; i < S; i++)
        for (int j = 0; j < S; j++)
            Sf[i][j] = 0.5f * (Wm[i][j] + Wm[j][i]);
    for (int i = 0; i < S; i++) Sf[i][i] = 0.f;
    for (int i = 0; i < S; i++) {
        float rs = 0.f;
        for (int j = 0; j < S; j++) rs += Sf[i][j];
        float inv = 1.f / fmaxf(rs, 1e-12f);
        for (int j = 0; j < S; j++) Sf[i][j] *= inv;
    }
    float P[4][4], Q[4][4], tr[Ll];
    for (int i = 0; i < S; i++)
        for (int j = 0; j < S; j++) P[i][j] = Sf[i][j];
    for (int l = 0; l < Ll; l++) {
        if (l) {
            for (int i = 0; i < S; i++)
                for (int j = 0; j < S; j++) {
                    float a = 0.f;
                    for (int k = 0; k < S; k++) a += P[i][k] * Sf[k][j];
                    Q[i][j] = a;
                }
            for (int i = 0; i < S; i++)
                for (int j = 0; j < S; j++) P[i][j] = Q[i][j];
        }
        float s = 0.f;
        for (int i = 0; i < S; i++) s += P[i][i];
        tr[l] = s;
    }
    for (int l = 0; l < Ll; l++) {
        float coeff = powf(GAMMAf, (float)(l + 1)) * softplusf(lg[l]);
        g_cs[which][l][f] = tr[l] * coeff;
    }
}

// ---------------- kernel 2: zero the motif accumulator ----------------
__global__ void zero_kernel() {
    int i = blockIdx.x * blockDim.x + threadIdx.x;
    if (i < Nn * 16) ((float*)g_Hm)[i] = 0.f;
}

// ---------------- motif response (round-9 version: 1 motif/thread) ----------------
template <int S>
__device__ __forceinline__ void motif_body(const float* __restrict__ A,
                                           const int* __restrict__ nodes,
                                           int M, int which, int bid) {
    int m = bid * 256 + threadIdx.x;
    if (m >= M) return;

    int nd[S];
#pragma unroll
    for (int i = 0; i < S; i++) nd[i] = nodes[m * S + i];

    float T[S][S];
#pragma unroll
    for (int i = 0; i < S; i++) {
        const float* rowp = A + (size_t)nd[i] * Nn;
#pragma unroll
        for (int j = 0; j < S; j++) T[i][j] = __ldg(rowp + nd[j]);
    }
#pragma unroll
    for (int i = 0; i < S; i++) {
        float rs = 0.f;
#pragma unroll
        for (int j = 0; j < S; j++) rs += T[i][j];
        float inv = 1.f / fmaxf(rs, 1e-12f);
#pragma unroll
        for (int j = 0; j < S; j++) T[i][j] *= inv;
    }

    float P[S][S], Q[S][S], tr[Ll];
#pragma unroll
    for (int i = 0; i < S; i++)
#pragma unroll
        for (int j = 0; j < S; j++) P[i][j] = T[i][j];
    {
        float s = 0.f;
#pragma unroll
        for (int i = 0; i < S; i++) s += P[i][i];
        tr[0] = s;
    }
#pragma unroll
    for (int l = 1; l < Ll; l++) {
#pragma unroll
        for (int i = 0; i < S; i++)
#pragma unroll
            for (int j = 0; j < S; j++) {
                float a = 0.f;
#pragma unroll
                for (int k = 0; k < S; k++) a += P[i][k] * T[k][j];
                Q[i][j] = a;
            }
        float s = 0.f;
#pragma unroll
        for (int i = 0; i < S; i++) {
#pragma unroll
            for (int j = 0; j < S; j++) P[i][j] = Q[i][j];
            s += P[i][i];
        }
        tr[l] = s;
    }

    float sims[Ff];
#pragma unroll
    for (int f = 0; f < Ff; f++) {
        float s = 0.f;
#pragma unroll
        for (int l = 0; l < Ll; l++) s += tr[l] * g_cs[which][l][f];
        sims[f] = s;
    }
    float mx = sims[0];
#pragma unroll
    for (int f = 1; f < Ff; f++) mx = fmaxf(mx, sims[f]);
    float e[Ff], es = 0.f;
#pragma unroll
    for (int f = 0; f < Ff; f++) { e[f] = expf(sims[f] - mx); es += e[f]; }
    float invs = 1.f / es;
    const float invS = 1.f / (float)S;
    float cb[Ff];
#pragma unroll
    for (int f = 0; f < Ff; f++) cb[f] = e[f] * invs * sims[f] * invS;

    int off = which * 8;
#pragma unroll
    for (int i = 0; i < S; i++) {
        float* p = &g_Hm[nd[i]][off];
        red4(p,     cb[0], cb[1], cb[2], cb[3]);
        red4(p + 4, cb[4], cb[5], cb[6], cb[7]);
    }
}

__global__ void motif_all_kernel(const float* __restrict__ A,
                                 const int* __restrict__ nt, int Mt, int nb3,
                                 const int* __restrict__ nc, int Mc) {
    if ((int)blockIdx.x < nb3)
        motif_body<3>(A, nt, Mt, 0, blockIdx.x);
    else
        motif_body<4>(A, nc, Mc, 1, blockIdx.x - nb3);
}

// ---------------- fused concat + LN + MLP ----------------
// 32 rows/block, 128 threads. Warp w owns cols [64w,64w+64), ALL 32 rows.
// Lane = (rowgrp 0-3, colgrp 0-7); thread tile 8 rows x 8 cols.
// Warp-private W slices via cp.async -> NO block barrier in GEMM mainloops.
#define ROWS  32
#define TPB   128
#define BK    8
#define XS    36                  // padded row stride in sXT

__global__ __launch_bounds__(TPB, 4) void mlp_kernel(
    const float* __restrict__ H_in, const float* __restrict__ ln_g,
    const float* __restrict__ ln_b,
    const float* __restrict__ W1, const float* __restrict__ b1,
    const float* __restrict__ W2, const float* __restrict__ b2,
    float* __restrict__ out) {
    __shared__ float sXT[IN_CH * XS];        // [k][row] transposed acts
    __shared__ float sWp[4][2][BK * 64];     // per-warp double-buffered W slice

    const int tid  = threadIdx.x;
    const int warp = tid >> 5;
    const int lane = tid & 31;
    const int rbase = blockIdx.x * ROWS;

    const int rg = lane >> 3;                // rowgrp 0-3 -> rows rg*8..+8
    const int cg = lane & 7;                 // colgrp 0-7 -> local cols cg*8..+8
    const int r0 = rg * 8;
    const int cloc = cg * 8;                 // within warp's 64-col slice
    const int cb   = warp * 64 + cloc;       // global col base

    // per-warp async fetch of its 64-col slice of one BK-row tile (2KB)
#define CPW(Wp, kbase, BUF)                                                  \
    {                                                                        \
        _Pragma("unroll")                                                    \
        for (int q = 0; q < 4; q++) {                                        \
            int p = q * 32 + lane;                                           \
            int kk = p >> 4, cc = (p & 15) << 2;                             \
            CPA16(&sWp[warp][BUF][kk * 64 + cc],                             \
                  &Wp[(size_t)((kbase) + kk) * HIDD + warp * 64 + cc]);      \
        }                                                                    \
        CP_COMMIT();                                                         \
    }
    // compute one BK tile from the warp-private buffer
#define CT(K0, BUF)                                                          \
    {                                                                        \
        _Pragma("unroll")                                                    \
        for (int kk = 0; kk < BK; kk++) {                                    \
            const float* xb = &sXT[(K0 + kk) * XS + r0];                     \
            float4 xa = *(const float4*)xb;                                  \
            float4 xc = *(const float4*)(xb + 4);                            \
            unsigned long long xp[8];                                        \
            DUP2(xp[0], __float_as_uint(xa.x));                              \
            DUP2(xp[1], __float_as_uint(xa.y));                              \
            DUP2(xp[2], __float_as_uint(xa.z));                              \
            DUP2(xp[3], __float_as_uint(xa.w));                              \
            DUP2(xp[4], __float_as_uint(xc.x));                              \
            DUP2(xp[5], __float_as_uint(xc.y));                              \
            DUP2(xp[6], __float_as_uint(xc.z));                              \
            DUP2(xp[7], __float_as_uint(xc.w));                              \
            const float* wb = &sWp[warp][BUF][kk * 64 + cloc];               \
            ulonglong2 wA = *(const ulonglong2*)wb;                          \
            ulonglong2 wB = *(const ulonglong2*)(wb + 4);                    \
            _Pragma("unroll")                                                \
            for (int i = 0; i < 8; i++) {                                    \
                FFMA2(acc[i][0], xp[i], wA.x);                               \
                FFMA2(acc[i][1], xp[i], wA.y);                               \
                FFMA2(acc[i][2], xp[i], wB.x);                               \
                FFMA2(acc[i][3], xp[i], wB.y);                               \
            }                                                                \
        }                                                                    \
    }

    // kick off W1 tile 0 fetch — latency hides under LN
    CPW(W1, 0, 0);

    // ---- LN: warp handles 8 rows; single gmem read ----
    {
        const int rl = warp * 8;
#pragma unroll
        for (int i = 0; i < 8; i++) {
            int r = rl + i;
            int grow = rbase + r;
            const float* hrow = H_in + (size_t)grow * D_INc;
            float vloc[9];
            float s = 0.f, s2 = 0.f;
#pragma unroll
            for (int q = 0; q < 9; q++) {
                int c = lane + q * 32;
                if (c < IN_CH) {
                    float v = (c < 16) ? g_Hm[grow][c] : __ldg(hrow + (c - 16));
                    vloc[q] = v;
                    s += v; s2 += v * v;
                }
            }
#pragma unroll
            for (int o = 16; o; o >>= 1) {
                s  += __shfl_xor_sync(0xffffffffu, s, o);
                s2 += __shfl_xor_sync(0xffffffffu, s2, o);
            }
            float mu = s * (1.f / IN_CH);
            float var = s2 * (1.f / IN_CH) - mu * mu;
            float rstd = rsqrtf(var + 1e-5f);
#pragma unroll
            for (int q = 0; q < 9; q++) {
                int c = lane + q * 32;
                if (c < IN_CH)
                    sXT[c * XS + r] = (vloc[q] - mu) * rstd * ln_g[c] + ln_b[c];
            }
        }
    }
    CP_WAIT0();
    __syncthreads();

    unsigned long long acc[8][4];
#pragma unroll
    for (int i = 0; i < 8; i++)
#pragma unroll
        for (int j = 0; j < 4; j++) acc[i][j] = 0ULL;

    // ---- GEMM1: x(32x272) @ W1(272x256) — barrier-free mainloop ----
    {
        const int NT = IN_CH / BK;       // 34
        for (int t = 0; t < NT; t++) {
            if (t + 1 < NT) CPW(W1, (t + 1) * BK, (t + 1) & 1);
            CT(t * BK, t & 1);
            if (t + 1 < NT) CP_WAIT0();
        }
    }

    // all warps must finish READING sXT before h overwrites it
    __syncthreads();

    // prefetch W2 tile 0 — hides under GELU math
    CPW(W2, 0, 0);

    // ---- bias + exact GELU -> transposed hidden into sXT ----
    {
        const float4 bA = *(const float4*)&b1[cb];
        const float4 bB = *(const float4*)&b1[cb + 4];
        const float bbv[8] = {bA.x, bA.y, bA.z, bA.w, bB.x, bB.y, bB.z, bB.w};
        float v[8][8];                    // [row][col]
#pragma unroll
        for (int i = 0; i < 8; i++)
#pragma unroll
            for (int j = 0; j < 4; j++) {
                unsigned lo, hi;
                UNPK2(lo, hi, acc[i][j]);
                float x0 = __uint_as_float(lo) + bbv[j * 2];
                float x1 = __uint_as_float(hi) + bbv[j * 2 + 1];
                v[i][j * 2]     = 0.5f * x0 * (1.f + erff(x0 * 0.7071067811865475f));
                v[i][j * 2 + 1] = 0.5f * x1 * (1.f + erff(x1 * 0.7071067811865475f));
                acc[i][j] = 0ULL;
            }
#pragma unroll
        for (int j = 0; j < 8; j++) {
            int c = cb + j;               // global hidden channel
            *(float4*)&sXT[c * XS + r0] =
                make_float4(v[0][j], v[1][j], v[2][j], v[3][j]);
            *(float4*)&sXT[c * XS + r0 + 4] =
                make_float4(v[4][j], v[5][j], v[6][j], v[7][j]);
        }
    }
    CP_WAIT0();
    __syncthreads();

    // ---- GEMM2: h(32x256) @ W2(256x256) — barrier-free mainloop ----
    {
        const int NT = HIDD / BK;        // 32
        for (int t = 0; t < NT; t++) {
            if (t + 1 < NT) CPW(W2, (t + 1) * BK, (t + 1) & 1);
            CT(t * BK, t & 1);
            if (t + 1 < NT) CP_WAIT0();
        }
    }

    // ---- bias + store ----
    {
        const float4 bA = *(const float4*)&b2[cb];
        const float4 bB = *(const float4*)&b2[cb + 4];
#pragma unroll
        for (int i = 0; i < 8; i++) {
            unsigned lo, hi;
            float v[8];
#pragma unroll
            for (int j = 0; j < 4; j++) {
                UNPK2(lo, hi, acc[i][j]);
                v[j * 2]     = __uint_as_float(lo);
                v[j * 2 + 1] = __uint_as_float(hi);
            }
            size_t base = (size_t)(rbase + r0 + i) * D_OUTc;
            *(float4*)&out[base + cb] =
                make_float4(v[0] + bA.x, v[1] + bA.y, v[2] + bA.z, v[3] + bA.w);
            *(float4*)&out[base + cb + 4] =
                make_float4(v[4] + bB.x, v[5] + bB.y, v[6] + bB.z, v[7] + bB.w);
        }
    }
}

// ---------------- launch ----------------
extern "C" void kernel_launch(void* const* d_in, const int* in_sizes, int n_in,
                              void* d_out, int out_size) {
    const float* A       = (const float*)d_in[0];
    const float* H_in    = (const float*)d_in[1];
    const float* Wt      = (const float*)d_in[2];
    const float* Wc      = (const float*)d_in[3];
    const float* lg      = (const float*)d_in[4];
    const float* ln_g    = (const float*)d_in[5];
    const float* ln_b    = (const float*)d_in[6];
    const float* W1      = (const float*)d_in[7];
    const float* b1      = (const float*)d_in[8];
    const float* W2      = (const float*)d_in[9];
    const float* b2      = (const float*)d_in[10];
    const int* nodes_tri = (const int*)d_in[11];
    const int* nodes_cl4 = (const int*)d_in[12];
    float* out = (float*)d_out;

    int M_tri = in_sizes[11] / 3;
    int M_cl4 = in_sizes[12] / 4;
    int nb3 = (M_tri + 255) / 256;
    int nb4 = (M_cl4 + 255) / 256;

    setup_kernel<<<1, 32>>>(Wt, Wc, lg);
    zero_kernel<<<(Nn * 16 + 255) / 256, 256>>>();
    motif_all_kernel<<<nb3 + nb4, 256>>>(A, nodes_tri, M_tri, nb3, nodes_cl4, M_cl4);
    mlp_kernel<<<Nn / ROWS, TPB>>>(H_in, ln_g, ln_b, W1, b1, W2, b2, out);
}

// round 14
// speedup vs baseline: 1.6655x; 1.6655x over previous
#include <cuda_runtime.h>
#include <math.h>

#define Nn     16384
#define D_INc  256
#define HIDD   256
#define D_OUTc 256
#define Ff     8
#define Ll     4
#define IN_CH  272          // 2*8 + 256
#define GAMMAf 0.5f

// ---------------- device scratch (no allocations allowed) ----------------
__device__ __align__(16) float g_cs[2][Ll][Ff];
__device__ __align__(16) float g_Hm[Nn][16];      // cols 0-7: tri, 8-15: cl4

__device__ __forceinline__ float softplusf(float x) {
    return (x > 20.f) ? x : log1pf(expf(x));
}

__device__ __forceinline__ void red4(float* p, float a, float b, float c, float d) {
    asm volatile("red.global.add.v4.f32 [%0], {%1, %2, %3, %4};"
                 :: "l"(p), "f"(a), "f"(b), "f"(c), "f"(d) : "memory");
}

// packed dual-fp32 FMA (Blackwell f32x2) -------------------------------
#define FFMA2(acc, a, b) \
    asm("fma.rn.f32x2 %0, %1, %2, %0;" : "+l"(acc) : "l"(a), "l"(b))
#define DUP2(p, x) \
    asm("mov.b64 %0, {%1, %1};" : "=l"(p) : "r"(x))
#define UNPK2(lo, hi, p) \
    asm("mov.b64 {%0, %1}, %2;" : "=r"(lo), "=r"(hi) : "l"(p))

// register-free async gmem->smem 16B copy (LDGSTS)
#define CPA16(dst, src) do {                                              \
    unsigned _s = (unsigned)__cvta_generic_to_shared(dst);                \
    asm volatile("cp.async.cg.shared.global [%0], [%1], 16;"              \
                 :: "r"(_s), "l"(src));                                   \
} while (0)
#define CP_COMMIT() asm volatile("cp.async.commit_group;" ::: "memory")
#define CP_WAIT0()  asm volatile("cp.async.wait_group 0;" ::: "memory")

// ---------------- kernel 1: zero accumulator + filter traces ----------------
__global__ void init_kernel(const float* __restrict__ Wt,
                            const float* __restrict__ Wc,
                            const float* __restrict__ lg) {
    int i = blockIdx.x * blockDim.x + threadIdx.x;
    if (i < Nn * 16) ((float*)g_Hm)[i] = 0.f;

    if (blockIdx.x == 0 && threadIdx.x < 16) {
        int t = threadIdx.x;
        int which = t >> 3;
        int f = t & 7;
        int S = which ? 4 : 3;
        const float* W = which ? (Wc + f * 16) : (Wt + f * 9);

        float Wm[4][4], Sf[4][4];
        for (int a = 0; a < S; a++)
            for (int b = 0; b < S; b++)
                Wm[a][b] = softplusf(W[a * S + b]);
        for (int a = 0; a < S; a++)
            for (int b = 0; b < S; b++)
                Sf[a][b] = 0.5f * (Wm[a][b] + Wm[b][a]);
        for (int a = 0; a < S; a++) Sf[a][a] = 0.f;
        for (int a = 0; a < S; a++) {
            float rs = 0.f;
            for (int b = 0; b < S; b++) rs += Sf[a][b];
            float inv = 1.f / fmaxf(rs, 1e-12f);
            for (int b = 0; b < S; b++) Sf[a][b] *= inv;
        }
        float P[4][4], Q[4][4], tr[Ll];
        for (int a = 0; a < S; a++)
            for (int b = 0; b < S; b++) P[a][b] = Sf[a][b];
        for (int l = 0; l < Ll; l++) {
            if (l) {
                for (int a = 0; a < S; a++)
                    for (int b = 0; b < S; b++) {
                        float acc = 0.f;
                        for (int k = 0; k < S; k++) acc += P[a][k] * Sf[k][b];
                        Q[a][b] = acc;
                    }
                for (int a = 0; a < S; a++)
                    for (int b = 0; b < S; b++) P[a][b] = Q[a][b];
            }
            float s = 0.f;
            for (int a = 0; a < S; a++) s += P[a][a];
            tr[l] = s;
        }
        for (int l = 0; l < Ll; l++) {
            float coeff = powf(GAMMAf, (float)(l + 1)) * softplusf(lg[l]);
            g_cs[which][l][f] = tr[l] * coeff;
        }
    }
}

// ---------------- motif response (1 motif/thread) ----------------
template <int S>
__device__ __forceinline__ void motif_body(const float* __restrict__ A,
                                           const int* __restrict__ nodes,
                                           int M, int which, int bid) {
    int m = bid * 256 + threadIdx.x;
    if (m >= M) return;

    int nd[S];
#pragma unroll
    for (int i = 0; i < S; i++) nd[i] = nodes[m * S + i];

    float T[S][S];
#pragma unroll
    for (int i = 0; i < S; i++) {
        const float* rowp = A + (size_t)nd[i] * Nn;
#pragma unroll
        for (int j = 0; j < S; j++) T[i][j] = __ldg(rowp + nd[j]);
    }
#pragma unroll
    for (int i = 0; i < S; i++) {
        float rs = 0.f;
#pragma unroll
        for (int j = 0; j < S; j++) rs += T[i][j];
        float inv = 1.f / fmaxf(rs, 1e-12f);
#pragma unroll
        for (int j = 0; j < S; j++) T[i][j] *= inv;
    }

    float P[S][S], Q[S][S], tr[Ll];
#pragma unroll
    for (int i = 0; i < S; i++)
#pragma unroll
        for (int j = 0; j < S; j++) P[i][j] = T[i][j];
    {
        float s = 0.f;
#pragma unroll
        for (int i = 0; i < S; i++) s += P[i][i];
        tr[0] = s;
    }
#pragma unroll
    for (int l = 1; l < Ll; l++) {
#pragma unroll
        for (int i = 0; i < S; i++)
#pragma unroll
            for (int j = 0; j < S; j++) {
                float a = 0.f;
#pragma unroll
                for (int k = 0; k < S; k++) a += P[i][k] * T[k][j];
                Q[i][j] = a;
            }
        float s = 0.f;
#pragma unroll
        for (int i = 0; i < S; i++) {
#pragma unroll
            for (int j = 0; j < S; j++) P[i][j] = Q[i][j];
            s += P[i][i];
        }
        tr[l] = s;
    }

    float sims[Ff];
#pragma unroll
    for (int f = 0; f < Ff; f++) {
        float s = 0.f;
#pragma unroll
        for (int l = 0; l < Ll; l++) s += tr[l] * g_cs[which][l][f];
        sims[f] = s;
    }
    float mx = sims[0];
#pragma unroll
    for (int f = 1; f < Ff; f++) mx = fmaxf(mx, sims[f]);
    float e[Ff], es = 0.f;
#pragma unroll
    for (int f = 0; f < Ff; f++) { e[f] = expf(sims[f] - mx); es += e[f]; }
    float invs = 1.f / es;
    const float invS = 1.f / (float)S;
    float cb[Ff];
#pragma unroll
    for (int f = 0; f < Ff; f++) cb[f] = e[f] * invs * sims[f] * invS;

    int off = which * 8;
#pragma unroll
    for (int i = 0; i < S; i++) {
        float* p = &g_Hm[nd[i]][off];
        red4(p,     cb[0], cb[1], cb[2], cb[3]);
        red4(p + 4, cb[4], cb[5], cb[6], cb[7]);
    }
}

__global__ void motif_all_kernel(const float* __restrict__ A,
                                 const int* __restrict__ nt, int Mt, int nb3,
                                 const int* __restrict__ nc, int Mc) {
    if ((int)blockIdx.x < nb3)
        motif_body<3>(A, nt, Mt, 0, blockIdx.x);
    else
        motif_body<4>(A, nc, Mc, 1, blockIdx.x - nb3);
}

// ---------------- fused concat + LN + MLP ----------------
// Round-9 structure (block-shared sW, cp.async double buffer, 1 barrier/tile).
// Lane remap: thread tile = 16 rows x 4 cols. lane = (rg 0-1)*16 + cg 0-15.
// x loads natural row-pairs (zero DUP2 on x); W needs only 4 DUP2/kk.
#define ROWS  32
#define TPB   128
#define BK    8
#define XS    36                  // padded row stride in sXT

__global__ __launch_bounds__(TPB, 4) void mlp_kernel(
    const float* __restrict__ H_in, const float* __restrict__ ln_g,
    const float* __restrict__ ln_b,
    const float* __restrict__ W1, const float* __restrict__ b1,
    const float* __restrict__ W2, const float* __restrict__ b2,
    float* __restrict__ out) {
    __shared__ float sXT[IN_CH * XS];      // [k][row] transposed acts
    __shared__ float sW[2][BK * HIDD];     // double-buffered W tile (block-wide)

    const int tid  = threadIdx.x;
    const int warp = tid >> 5;
    const int lane = tid & 31;
    const int rbase = blockIdx.x * ROWS;

    const int rg = lane >> 4;              // 0-1  -> rows rg*16 .. +16
    const int cg = lane & 15;              // 0-15 -> cols warp*64 + cg*4 .. +4
    const int r0 = rg * 16;
    const int cb = warp * 64 + cg * 4;     // global output col base

    // block-wide async fetch of one BK-row W tile (round-9 proven pattern)
#define CPA_TILE(Wp, kbase, BUF)                                             \
    {                                                                        \
        _Pragma("unroll")                                                    \
        for (int q = 0; q < 4; q++) {                                        \
            int p = q * TPB + tid;                                           \
            int kk = p >> 6, cc = (p & 63) << 2;                             \
            CPA16(&sW[BUF][kk * HIDD + cc],                                  \
                  &Wp[(size_t)((kbase) + kk) * HIDD + cc]);                  \
        }                                                                    \
        CP_COMMIT();                                                         \
    }
#define COMPUTE_TILE(K0, BUF)                                                \
    {                                                                        \
        _Pragma("unroll")                                                    \
        for (int kk = 0; kk < BK; kk++) {                                    \
            const float* xb = &sXT[(K0 + kk) * XS + r0];                     \
            ulonglong2 x01 = *(const ulonglong2*)xb;        /* rows 0-3 */   \
            ulonglong2 x23 = *(const ulonglong2*)(xb + 4);  /* rows 4-7 */   \
            ulonglong2 x45 = *(const ulonglong2*)(xb + 8);                   \
            ulonglong2 x67 = *(const ulonglong2*)(xb + 12);                  \
            float4 wv = *(const float4*)&sW[BUF][kk * HIDD + cb];            \
            unsigned long long wd0, wd1, wd2, wd3;                           \
            DUP2(wd0, __float_as_uint(wv.x));                                \
            DUP2(wd1, __float_as_uint(wv.y));                                \
            DUP2(wd2, __float_as_uint(wv.z));                                \
            DUP2(wd3, __float_as_uint(wv.w));                                \
            FFMA2(acc[0][0], x01.x, wd0); FFMA2(acc[0][1], x01.x, wd1);      \
            FFMA2(acc[0][2], x01.x, wd2); FFMA2(acc[0][3], x01.x, wd3);      \
            FFMA2(acc[1][0], x01.y, wd0); FFMA2(acc[1][1], x01.y, wd1);      \
            FFMA2(acc[1][2], x01.y, wd2); FFMA2(acc[1][3], x01.y, wd3);      \
            FFMA2(acc[2][0], x23.x, wd0); FFMA2(acc[2][1], x23.x, wd1);      \
            FFMA2(acc[2][2], x23.x, wd2); FFMA2(acc[2][3], x23.x, wd3);      \
            FFMA2(acc[3][0], x23.y, wd0); FFMA2(acc[3][1], x23.y, wd1);      \
            FFMA2(acc[3][2], x23.y, wd2); FFMA2(acc[3][3], x23.y, wd3);      \
            FFMA2(acc[4][0], x45.x, wd0); FFMA2(acc[4][1], x45.x, wd1);      \
            FFMA2(acc[4][2], x45.x, wd2); FFMA2(acc[4][3], x45.x, wd3);      \
            FFMA2(acc[5][0], x45.y, wd0); FFMA2(acc[5][1], x45.y, wd1);      \
            FFMA2(acc[5][2], x45.y, wd2); FFMA2(acc[5][3], x45.y, wd3);      \
            FFMA2(acc[6][0], x67.x, wd0); FFMA2(acc[6][1], x67.x, wd1);      \
            FFMA2(acc[6][2], x67.x, wd2); FFMA2(acc[6][3], x67.x, wd3);      \
            FFMA2(acc[7][0], x67.y, wd0); FFMA2(acc[7][1], x67.y, wd1);      \
            FFMA2(acc[7][2], x67.y, wd2); FFMA2(acc[7][3], x67.y, wd3);      \
        }                                                                    \
    }

    // kick off W1 tile 0 fetch — latency hides under LN
    CPA_TILE(W1, 0, 0);

    // ---- LN: warp handles 8 rows; single gmem read ----
    {
        const int rl = warp * 8;
#pragma unroll
        for (int i = 0; i < 8; i++) {
            int r = rl + i;
            int grow = rbase + r;
            const float* hrow = H_in + (size_t)grow * D_INc;
            float vloc[9];
            float s = 0.f, s2 = 0.f;
#pragma unroll
            for (int q = 0; q < 9; q++) {
                int c = lane + q * 32;
                if (c < IN_CH) {
                    float v = (c < 16) ? g_Hm[grow][c] : __ldg(hrow + (c - 16));
                    vloc[q] = v;
                    s += v; s2 += v * v;
                }
            }
#pragma unroll
            for (int o = 16; o; o >>= 1) {
                s  += __shfl_xor_sync(0xffffffffu, s, o);
                s2 += __shfl_xor_sync(0xffffffffu, s2, o);
            }
            float mu = s * (1.f / IN_CH);
            float var = s2 * (1.f / IN_CH) - mu * mu;
            float rstd = rsqrtf(var + 1e-5f);
#pragma unroll
            for (int q = 0; q < 9; q++) {
                int c = lane + q * 32;
                if (c < IN_CH)
                    sXT[c * XS + r] = (vloc[q] - mu) * rstd * ln_g[c] + ln_b[c];
            }
        }
    }
    CP_WAIT0();
    __syncthreads();

    unsigned long long acc[8][4];      // [row-pair][col]
#pragma unroll
    for (int i = 0; i < 8; i++)
#pragma unroll
        for (int j = 0; j < 4; j++) acc[i][j] = 0ULL;

    // ---- GEMM1: x(32x272) @ W1(272x256) ----
    {
        const int NT = IN_CH / BK;       // 34
        for (int t = 0; t < NT; t++) {
            if (t + 1 < NT) CPA_TILE(W1, (t + 1) * BK, (t + 1) & 1);
            COMPUTE_TILE(t * BK, t & 1);
            if (t + 1 < NT) CP_WAIT0();
            __syncthreads();
        }
    }

    // prefetch W2 tile 0 — hides under GELU math
    CPA_TILE(W2, 0, 0);

    // ---- bias + exact GELU -> transposed hidden into sXT ----
    {
        const float4 bv = *(const float4*)&b1[cb];
        const float bbv[4] = {bv.x, bv.y, bv.z, bv.w};
#pragma unroll
        for (int rp = 0; rp < 8; rp++) {
#pragma unroll
            for (int j = 0; j < 4; j++) {
                unsigned lo, hi;
                UNPK2(lo, hi, acc[rp][j]);
                float x0 = __uint_as_float(lo) + bbv[j];
                float x1 = __uint_as_float(hi) + bbv[j];
                x0 = 0.5f * x0 * (1.f + erff(x0 * 0.7071067811865475f));
                x1 = 0.5f * x1 * (1.f + erff(x1 * 0.7071067811865475f));
                *(float2*)&sXT[(cb + j) * XS + r0 + rp * 2] = make_float2(x0, x1);
                acc[rp][j] = 0ULL;
            }
        }
    }
    CP_WAIT0();
    __syncthreads();

    // ---- GEMM2: h(32x256) @ W2(256x256) ----
    {
        const int NT = HIDD / BK;        // 32
        for (int t = 0; t < NT; t++) {
            if (t + 1 < NT) CPA_TILE(W2, (t + 1) * BK, (t + 1) & 1);
            COMPUTE_TILE(t * BK, t & 1);
            if (t + 1 < NT) CP_WAIT0();
            __syncthreads();
        }
    }

    // ---- bias + store ----
    {
        const float4 bv = *(const float4*)&b2[cb];
#pragma unroll
        for (int rp = 0; rp < 8; rp++) {
            unsigned lo0, hi0, lo1, hi1, lo2, hi2, lo3, hi3;
            UNPK2(lo0, hi0, acc[rp][0]);
            UNPK2(lo1, hi1, acc[rp][1]);
            UNPK2(lo2, hi2, acc[rp][2]);
            UNPK2(lo3, hi3, acc[rp][3]);
            size_t rowA = (size_t)(rbase + r0 + rp * 2) * D_OUTc;
            *(float4*)&out[rowA + cb] = make_float4(
                __uint_as_float(lo0) + bv.x, __uint_as_float(lo1) + bv.y,
                __uint_as_float(lo2) + bv.z, __uint_as_float(lo3) + bv.w);
            *(float4*)&out[rowA + D_OUTc + cb] = make_float4(
                __uint_as_float(hi0) + bv.x, __uint_as_float(hi1) + bv.y,
                __uint_as_float(hi2) + bv.z, __uint_as_float(hi3) + bv.w);
        }
    }
}

// ---------------- launch ----------------
extern "C" void kernel_launch(void* const* d_in, const int* in_sizes, int n_in,
                              void* d_out, int out_size) {
    const float* A       = (const float*)d_in[0];
    const float* H_in    = (const float*)d_in[1];
    const float* Wt      = (const float*)d_in[2];
    const float* Wc      = (const float*)d_in[3];
    const float* lg      = (const float*)d_in[4];
    const float* ln_g    = (const float*)d_in[5];
    const float* ln_b    = (const float*)d_in[6];
    const float* W1      = (const float*)d_in[7];
    const float* b1      = (const float*)d_in[8];
    const float* W2      = (const float*)d_in[9];
    const float* b2      = (const float*)d_in[10];
    const int* nodes_tri = (const int*)d_in[11];
    const int* nodes_cl4 = (const int*)d_in[12];
    float* out = (float*)d_out;

    int M_tri = in_sizes[11] / 3;
    int M_cl4 = in_sizes[12] / 4;
    int nb3 = (M_tri + 255) / 256;
    int nb4 = (M_cl4 + 255) / 256;

    init_kernel<<<(Nn * 16 + 255) / 256, 256>>>(Wt, Wc, lg);
    motif_all_kernel<<<nb3 + nb4, 256>>>(A, nodes_tri, M_tri, nb3, nodes_cl4, M_cl4);
    mlp_kernel<<<Nn / ROWS, TPB>>>(H_in, ln_g, ln_b, W1, b1, W2, b2, out);
}